// round 6
// baseline (speedup 1.0000x reference)
#include <cuda_runtime.h>
#include <type_traits>
#include <cstddef>

namespace so3 {

constexpr int LMAX  = 8;
constexpr int NCOEF = (LMAX + 1) * (LMAX + 1);   // 81 per batch per array
constexpr int TPB   = 128;

// ---------------- compile-time math (host+device so device lambdas may name them) ----------------
__host__ __device__ constexpr double fact(int n) { double r = 1.0; for (int i = 2; i <= n; ++i) r *= (double)i; return r; }
__host__ __device__ constexpr double csqrt(double x) {
    if (x <= 0.0) return 0.0;
    double g = x > 1.0 ? x : 1.0;
    for (int i = 0; i < 64; ++i) g = 0.5 * (g + x / g);
    return g;
}
__host__ __device__ constexpr int iabs(int x) { return x < 0 ? -x : x; }
__host__ __device__ constexpr int imin(int a, int b) { return a < b ? a : b; }
__host__ __device__ constexpr int imax(int a, int b) { return a > b ? a : b; }

// Clebsch-Gordan <j1 m1 j2 m2 | j3 m3>, Racah formula (matches reference)
__host__ __device__ constexpr double cg(int j1, int m1, int j2, int m2, int j3, int m3) {
    if (m1 + m2 != m3) return 0.0;
    if (j3 < iabs(j1 - j2) || j3 > j1 + j2) return 0.0;
    if (iabs(m1) > j1 || iabs(m2) > j2 || iabs(m3) > j3) return 0.0;
    double pre = csqrt((2.0 * j3 + 1.0) * fact(j1 + j2 - j3) * fact(j1 - j2 + j3) *
                       fact(-j1 + j2 + j3) / fact(j1 + j2 + j3 + 1));
    pre *= csqrt(fact(j1 + m1) * fact(j1 - m1) * fact(j2 + m2) * fact(j2 - m2) *
                 fact(j3 + m3) * fact(j3 - m3));
    int kmin = imax(0, imax(j2 - j3 - m1, j1 - j3 + m2));
    int kmax = imin(j1 + j2 - j3, imin(j1 - m1, j2 + m2));
    double s = 0.0;
    for (int k = kmin; k <= kmax; ++k) {
        double d = fact(k) * fact(j1 + j2 - j3 - k) * fact(j1 - m1 - k) *
                   fact(j2 + m2 - k) * fact(j3 - j2 + m1 + k) * fact(j3 - j1 - m2 + k);
        s += ((k & 1) ? -1.0 : 1.0) / d;
    }
    return pre * s;
}

// ---------------- output index maps (mirror reference builders) ----------------
__host__ __device__ constexpr int full_index(int a, int b, int c) {
    int idx = 0;
    for (int l1 = 0; l1 <= LMAX; ++l1)
        for (int l2 = l1; l2 <= LMAX; ++l2)
            for (int lv = l2 - l1; lv <= imin(l1 + l2, LMAX); ++lv) {
                if (l1 == a && l2 == b && lv == c) return idx;
                ++idx;
            }
    return -1;
}
__host__ __device__ constexpr int count_full() {
    int idx = 0;
    for (int l1 = 0; l1 <= LMAX; ++l1)
        for (int l2 = l1; l2 <= LMAX; ++l2)
            for (int lv = l2 - l1; lv <= imin(l1 + l2, LMAX); ++lv) ++idx;
    return idx;
}
constexpr int NFULL = count_full();
static_assert(NFULL == 215, "FULL map size mismatch");

// returns found ? index : 1000 + total_count
__host__ __device__ constexpr int power_index_impl(int a, int b, int c) {
    int idx = 0;
    for (int l2 = 2; l2 <= LMAX; ++l2) {
        if (a == 1 && b == l2 && c == l2 - 1) return idx;
        ++idx;
        if (l2 >= 4 && (l2 - 1) + 1 <= imin(l2 + 1, LMAX)) {
            if (a == 1 && b == l2 && c == l2) return idx;
            ++idx;
        }
    }
    for (int l2 = 3; l2 <= LMAX; ++l2) {
        if (a == 2 && b == l2 && c == l2 - 2) return idx;
        ++idx;
        if ((l2 - 2) + 1 <= imin(l2 + 2, LMAX)) {
            if (a == 2 && b == l2 && c == l2 - 1) return idx;
            ++idx;
        }
    }
    if (LMAX >= 3) {
        if (a == 3 && b == 3 && c == 2) return idx;
        ++idx;
    }
    for (int l2 = 4; l2 <= LMAX; ++l2) {
        if (a == 3 && b == l2 && c == l2 - 3) return idx;
        ++idx;
        if ((l2 % 2 == 1) && l2 >= 5) {
            if ((l2 - 3) + 1 <= imin(l2 + 3, LMAX)) {
                if (a == 3 && b == l2 && c == l2 - 2) return idx;
                ++idx;
            }
            if ((l2 - 3) + 2 <= imin(l2 + 3, LMAX)) {
                if (a == 3 && b == l2 && c == l2 - 1) return idx;
                ++idx;
            }
        }
    }
    return 1000 + idx;
}
__host__ __device__ constexpr int power_index(int a, int b, int c) {
    return power_index_impl(a, b, c) >= 1000 ? -1 : power_index_impl(a, b, c);
}
constexpr int NPOWER = power_index_impl(-9, -9, -9) - 1000;
static_assert(NPOWER == 34, "POWER map size mismatch");
constexpr int NOUT = NFULL + NPOWER;   // 249

// ---------------- static-for ----------------
template <int I, int N, class F>
__device__ __forceinline__ void sfor(F&& f) {
    if constexpr (I < N) {
        f(std::integral_constant<int, I>{});
        sfor<I + 1, N>(f);
    }
}

// F_l^m accessors for any m in [-l, l]; negative m via F_l^{-m} = (-1)^m conj(F_l^m)
template <int l, int m>
__device__ __forceinline__ float Fre(const float (&fr)[LMAX + 1][LMAX + 1]) {
    if constexpr (m >= 0) return fr[l][m];
    else if constexpr ((-m) & 1) return -fr[l][-m];
    else return fr[l][-m];
}
template <int l, int m>
__device__ __forceinline__ float Fim(const float (&fi)[LMAX + 1][LMAX + 1]) {
    if constexpr (m >= 0) return fi[l][m];
    else if constexpr ((-m) & 1) return fi[l][-m];   // (-1)^m * (-fi) = +fi for odd m
    else return -fi[l][-m];
}

// ---------------- kernel ----------------
__global__ void __launch_bounds__(TPB) bispec_kernel(
    const float* __restrict__ cre, const float* __restrict__ cim,
    float* __restrict__ out, int batch)
{
    __shared__ float stage[TPB * NCOEF];

    const int blk_base = blockIdx.x * TPB;
    const int b = blk_base + threadIdx.x;
    const bool active = (b < batch);

    const int nvalid = imin(TPB, batch - blk_base);
    const int nf  = (nvalid > 0 ? nvalid : 0) * NCOEF;
    const int nf4 = nf >> 2;

    float fr[LMAX + 1][LMAX + 1];
    float fi[LMAX + 1][LMAX + 1];

    // ---- stage REAL coefficients (coalesced float4), copy to regs ----
    {
        const float* gsrc = cre + (size_t)blk_base * NCOEF;
        for (int i = threadIdx.x; i < nf4; i += TPB)
            reinterpret_cast<float4*>(stage)[i] = reinterpret_cast<const float4*>(gsrc)[i];
        for (int i = nf4 * 4 + threadIdx.x; i < nf; i += TPB)
            stage[i] = gsrc[i];
    }
    __syncthreads();
    if (active) {
        const float* my = stage + threadIdx.x * NCOEF;
        sfor<0, LMAX + 1>([&](auto Lc) {
            constexpr int l = decltype(Lc)::value;
            sfor<0, l + 1>([&](auto Mc) {
                constexpr int m = decltype(Mc)::value;
                fr[l][m] = my[l * (LMAX + 1) + m];
            });
        });
    }
    __syncthreads();

    // ---- stage IMAG coefficients ----
    {
        const float* gsrc = cim + (size_t)blk_base * NCOEF;
        for (int i = threadIdx.x; i < nf4; i += TPB)
            reinterpret_cast<float4*>(stage)[i] = reinterpret_cast<const float4*>(gsrc)[i];
        for (int i = nf4 * 4 + threadIdx.x; i < nf; i += TPB)
            stage[i] = gsrc[i];
    }
    __syncthreads();
    if (active) {
        const float* my = stage + threadIdx.x * NCOEF;
        sfor<0, LMAX + 1>([&](auto Lc) {
            constexpr int l = decltype(Lc)::value;
            sfor<0, l + 1>([&](auto Mc) {
                constexpr int m = decltype(Mc)::value;
                fi[l][m] = my[l * (LMAX + 1) + m];
            });
        });
    }

    if (!active) return;

    float* ob = out + (size_t)b * NOUT;

    // ---- fully unrolled bispectrum ----
    sfor<0, LMAX + 1>([&](auto L1c) {
        constexpr int l1 = decltype(L1c)::value;
        sfor<l1, LMAX + 1>([&](auto L2c) {
            constexpr int l2 = decltype(L2c)::value;
            constexpr int lomin = l2 - l1;
            constexpr int lomax = imin(l1 + l2, LMAX);
            constexpr int nlo = lomax - lomin + 1;

            float beta[nlo];
            float pw[nlo];
            sfor<0, nlo>([&](auto Ic) {
                constexpr int i = decltype(Ic)::value;
                beta[i] = 0.f; pw[i] = 0.f;
            });

            sfor<-(l1 + l2), l1 + l2 + 1>([&](auto MMc) {
                constexpr int M = decltype(MMc)::value;
                constexpr int lstart = imax(lomin, iabs(M));
                if constexpr (lstart <= lomax) {
                    constexpr int ng = lomax - lstart + 1;
                    float gre[ng], gim[ng];
                    sfor<0, ng>([&](auto Ic) {
                        constexpr int i = decltype(Ic)::value;
                        gre[i] = 0.f; gim[i] = 0.f;
                    });

                    constexpr int m1lo = imax(-l1, M - l2);
                    constexpr int m1hi = imin(l1, M + l2);
                    sfor<m1lo, m1hi + 1>([&](auto M1c) {
                        constexpr int m1 = decltype(M1c)::value;
                        constexpr int m2 = M - m1;
                        // l1==l2: fold (m1,m2)+(m2,m1), keep m1<=m2 only
                        if constexpr (!(l1 == l2 && m1 > m2)) {
                            float are = Fre<l1, m1>(fr), aim = Fim<l1, m1>(fi);
                            float bre = Fre<l2, m2>(fr), bim = Fim<l2, m2>(fi);
                            float p_re = are * bre - aim * bim;
                            float p_im = are * bim + aim * bre;
                            sfor<lstart, lomax + 1>([&](auto LOc) {
                                constexpr int lo = decltype(LOc)::value;
                                constexpr double c0 = cg(l1, m1, l2, m2, lo, M);
                                constexpr double cc = (l1 == l2 && m1 < m2)
                                    ? c0 + cg(l1, m2, l2, m1, lo, M) : c0;
                                if constexpr (cc != 0.0) {
                                    constexpr float cf = (float)cc;
                                    gre[lo - lstart] += cf * p_re;   // FFMA-imm
                                    gim[lo - lstart] += cf * p_im;   // FFMA-imm
                                }
                            });
                        }
                    });

                    // contract with conj(F_lo^M) (real part) + CG-power norms
                    sfor<lstart, lomax + 1>([&](auto LOc) {
                        constexpr int lo = decltype(LOc)::value;
                        float g_re = gre[lo - lstart], g_im = gim[lo - lstart];
                        float f3re = Fre<lo, M>(fr), f3im = Fim<lo, M>(fi);
                        beta[lo - lomin] += g_re * f3re + g_im * f3im;
                        if constexpr (power_index(l1, l2, lo) >= 0) {
                            pw[lo - lomin] += g_re * g_re + g_im * g_im;
                        }
                    });
                }
            });

            // write outputs for this (l1,l2) block
            sfor<lomin, lomax + 1>([&](auto LOc) {
                constexpr int lo = decltype(LOc)::value;
                constexpr int fidx = full_index(l1, l2, lo);
                ob[fidx] = beta[lo - lomin];
                constexpr int pidx = power_index(l1, l2, lo);
                if constexpr (pidx >= 0) {
                    ob[NFULL + pidx] = pw[lo - lomin];
                }
            });
        });
    });
}

} // namespace so3

extern "C" void kernel_launch(void* const* d_in, const int* in_sizes, int n_in,
                              void* d_out, int out_size) {
    const float* cre = (const float*)d_in[0];
    const float* cim = (const float*)d_in[1];
    float* out = (float*)d_out;
    const int batch = in_sizes[0] / so3::NCOEF;
    const int blocks = (batch + so3::TPB - 1) / so3::TPB;
    so3::bispec_kernel<<<blocks, so3::TPB>>>(cre, cim, out, batch);
}